// round 2
// baseline (speedup 1.0000x reference)
#include <cuda_runtime.h>

#define L 2048
#define B 32
#define H 1024
#define GCH 16            // g-chunks for K1 partials
#define GSZ (H / GCH)     // 64
#define HT  64            // h-tile width in K1
#define LTILES 32
#define LPT (L / LTILES)  // 64 l-positions per K2 block
#define LPW (LPT / 8)     // 8 l's per warp

// Scratch (allocation-free rule: __device__ globals)
__device__ float g_vpart[GCH][B][H];   // 2 MB partial v
__device__ float g_energy[B][L];       // 256 KB energies

// ---------------------------------------------------------------------------
// K1: v_part[gc][b][h] = sum_{g in chunk gc} hidden[b,g] * W[g,h]
// grid (H/HT=16, GCH=16) = 256 blocks, block 256 = 64 hcols x 4 b-quarters.
// Each thread: 64 independent W loads, 8 accumulators (8 b's).
// ---------------------------------------------------------------------------
__global__ void k1_proj(const float* __restrict__ hidden,
                        const float* __restrict__ W) {
    const int tid  = threadIdx.x;
    const int hcol = blockIdx.x * HT + (tid & (HT - 1));
    const int bq   = tid >> 6;            // 0..3  -> b range [bq*8, bq*8+8)
    const int g0   = blockIdx.y * GSZ;

    __shared__ float hsh[B][GSZ];         // 8 KB hidden chunk
    for (int i = tid; i < B * GSZ; i += 256) {
        const int bb = i / GSZ, g = i % GSZ;
        hsh[bb][g] = hidden[(size_t)bb * H + g0 + g];
    }
    __syncthreads();

    float acc[8];
    #pragma unroll
    for (int j = 0; j < 8; j++) acc[j] = 0.f;

    #pragma unroll 8
    for (int g = 0; g < GSZ; g++) {
        const float w = W[(size_t)(g0 + g) * H + hcol];
        #pragma unroll
        for (int j = 0; j < 8; j++)
            acc[j] += w * hsh[bq * 8 + j][g];   // smem broadcast
    }

    #pragma unroll
    for (int j = 0; j < 8; j++)
        g_vpart[blockIdx.y][bq * 8 + j][hcol] = acc[j];
}

// ---------------------------------------------------------------------------
// K2: energies[b][l] = dot(enc[l,b,:], v[b,:])
// grid (LTILES=32, B), block 256 (8 warps, 8 l's per warp, processed in pairs).
// v reduced from GCH partials into 4 KB smem once per block (L2-resident).
// ---------------------------------------------------------------------------
__global__ void k2_energy(const float* __restrict__ enc) {
    const int b  = blockIdx.y;
    const int l0 = blockIdx.x * LPT;
    const int tid = threadIdx.x;

    __shared__ float4 vsh[H / 4];   // 4 KB
    {
        float4 s = make_float4(0.f, 0.f, 0.f, 0.f);
        #pragma unroll
        for (int p = 0; p < GCH; p++) {
            const float4 v = *(const float4*)&g_vpart[p][b][tid * 4];
            s.x += v.x; s.y += v.y; s.z += v.z; s.w += v.w;
        }
        vsh[tid] = s;
    }
    __syncthreads();

    const int warp = tid >> 5, lane = tid & 31;
    const float4* __restrict__ enc4 = (const float4*)enc;

    #pragma unroll
    for (int i = 0; i < LPW; i += 2) {
        const int la = l0 + warp * LPW + i;
        const int lb = la + 1;
        const size_t ba = ((size_t)la * B + b) * (H / 4);
        const size_t bb = ((size_t)lb * B + b) * (H / 4);
        float a0 = 0.f, a1 = 0.f;
        #pragma unroll
        for (int k = 0; k < 8; k++) {
            const float4 v  = vsh[k * 32 + lane];
            const float4 e0 = enc4[ba + k * 32 + lane];
            const float4 e1 = enc4[bb + k * 32 + lane];
            a0 += e0.x * v.x + e0.y * v.y + e0.z * v.z + e0.w * v.w;
            a1 += e1.x * v.x + e1.y * v.y + e1.z * v.z + e1.w * v.w;
        }
        #pragma unroll
        for (int s = 16; s; s >>= 1) {
            a0 += __shfl_down_sync(0xffffffffu, a0, s);
            a1 += __shfl_down_sync(0xffffffffu, a1, s);
        }
        if (lane == 0) {
            g_energy[b][la] = a0;
            g_energy[b][lb] = a1;
        }
    }
}

// ---------------------------------------------------------------------------
// K3: masked softmax per batch row. grid B, block 1024, 2 l's per thread.
// out[b,0,l] = valid ? exp(e - max)/sum : 0
// ---------------------------------------------------------------------------
__global__ void k3_softmax(const int* __restrict__ lengths,
                           float* __restrict__ out) {
    const int b   = blockIdx.x;
    const int len = lengths[b];
    const int tid = threadIdx.x;

    float e0 = g_energy[b][tid];
    float e1 = g_energy[b][tid + 1024];
    float mx = -3.4e38f;
    if (tid        < len) mx = e0;
    if (tid + 1024 < len) mx = fmaxf(mx, e1);

    __shared__ float red[32];
    #pragma unroll
    for (int s = 16; s; s >>= 1)
        mx = fmaxf(mx, __shfl_xor_sync(0xffffffffu, mx, s));
    if ((tid & 31) == 0) red[tid >> 5] = mx;
    __syncthreads();
    if (tid < 32) {
        float m = red[tid];
        #pragma unroll
        for (int s = 16; s; s >>= 1)
            m = fmaxf(m, __shfl_xor_sync(0xffffffffu, m, s));
        red[tid] = m;
    }
    __syncthreads();
    mx = red[0];
    __syncthreads();   // protect red[] before reuse

    const float x0 = (tid        < len) ? expf(e0 - mx) : 0.f;
    const float x1 = (tid + 1024 < len) ? expf(e1 - mx) : 0.f;
    float sum = x0 + x1;
    #pragma unroll
    for (int s = 16; s; s >>= 1)
        sum += __shfl_xor_sync(0xffffffffu, sum, s);
    if ((tid & 31) == 0) red[tid >> 5] = sum;
    __syncthreads();
    if (tid < 32) {
        float m = red[tid];
        #pragma unroll
        for (int s = 16; s; s >>= 1)
            m += __shfl_xor_sync(0xffffffffu, m, s);
        red[tid] = m;
    }
    __syncthreads();
    const float inv = 1.f / red[0];

    out[(size_t)b * L + tid]        = x0 * inv;
    out[(size_t)b * L + tid + 1024] = x1 * inv;
}

// ---------------------------------------------------------------------------
extern "C" void kernel_launch(void* const* d_in, const int* in_sizes, int n_in,
                              void* d_out, int out_size) {
    const float* hidden  = (const float*)d_in[0];   // [1,B,H]
    const float* enc     = (const float*)d_in[1];   // [L,B,H]
    const float* W       = (const float*)d_in[2];   // [H,H]
    // d_in[3] = bias — provably cancels in softmax, unused
    const int*   lengths = (const int*)d_in[4];     // [B]
    float* out = (float*)d_out;                     // [B,1,L]

    dim3 g1(H / HT, GCH);
    k1_proj<<<g1, 256>>>(hidden, W);

    dim3 g2(LTILES, B);
    k2_energy<<<g2, 256>>>(enc);

    k3_softmax<<<B, 1024>>>(lengths, out);
}

// round 3
// speedup vs baseline: 1.2472x; 1.2472x over previous
#include <cuda_runtime.h>

#define L 2048
#define B 32
#define H 1024
#define H4 (H / 4)
#define GCH 64            // g-chunks for K1 partials
#define GSZ (H / GCH)     // 16
#define LTILES 32
#define LPT (L / LTILES)  // 64 l-positions per K2 block
#define LPW (LPT / 8)     // 8 l's per warp

// Scratch (allocation-free rule: __device__ globals)
__device__ float g_vpart[GCH][B][H];   // 8 MB partial v
__device__ float g_v[B][H];            // 128 KB reduced v
__device__ float g_energy[B][L];       // 256 KB energies

// ---------------------------------------------------------------------------
// K1: v_part[gc][b][h] = sum_{g in chunk gc} hidden[b,g] * W[g,h]
// grid (H/256=4, GCH=64) = 256 blocks, block 256 = 64 h-quads x 4 b-quarters.
// Thread: 4 h-cols (float4) x 8 b's, GSZ=16 g's -> 16 LDG.128 + 512 FMA.
// ---------------------------------------------------------------------------
__global__ void k1_proj(const float* __restrict__ hidden,
                        const float* __restrict__ W) {
    const int tid   = threadIdx.x;
    const int hquad = tid & 63;                     // 0..63
    const int hcol  = blockIdx.x * 256 + hquad * 4; // float4 col base
    const int bq    = tid >> 6;                     // 0..3 -> b in [bq*8, bq*8+8)
    const int g0    = blockIdx.y * GSZ;

    __shared__ float4 hsh[B][GSZ / 4];              // 2 KB: hidden[g0..g0+16) per b
    if (tid < B * (GSZ / 4)) {
        const int bb = tid >> 2, gg = tid & 3;
        hsh[bb][gg] = ((const float4*)hidden)[(size_t)bb * H4 + (g0 >> 2) + gg];
    }
    __syncthreads();

    float4 acc[8];
    #pragma unroll
    for (int j = 0; j < 8; j++) acc[j] = make_float4(0.f, 0.f, 0.f, 0.f);

    const float4* __restrict__ W4 = (const float4*)W;
    #pragma unroll
    for (int gg = 0; gg < GSZ / 4; gg++) {
        const int g = g0 + gg * 4;
        const float4 w0 = W4[((size_t)(g + 0) * H + hcol) >> 2];
        const float4 w1 = W4[((size_t)(g + 1) * H + hcol) >> 2];
        const float4 w2 = W4[((size_t)(g + 2) * H + hcol) >> 2];
        const float4 w3 = W4[((size_t)(g + 3) * H + hcol) >> 2];
        #pragma unroll
        for (int j = 0; j < 8; j++) {
            const float4 hb = hsh[bq * 8 + j][gg];  // (h[g], h[g+1], h[g+2], h[g+3])
            acc[j].x += w0.x * hb.x + w1.x * hb.y + w2.x * hb.z + w3.x * hb.w;
            acc[j].y += w0.y * hb.x + w1.y * hb.y + w2.y * hb.z + w3.y * hb.w;
            acc[j].z += w0.z * hb.x + w1.z * hb.y + w2.z * hb.z + w3.z * hb.w;
            acc[j].w += w0.w * hb.x + w1.w * hb.y + w2.w * hb.z + w3.w * hb.w;
        }
    }

    #pragma unroll
    for (int j = 0; j < 8; j++)
        *(float4*)&g_vpart[blockIdx.y][bq * 8 + j][hcol] = acc[j];
}

// ---------------------------------------------------------------------------
// K1b: g_v[b][h] = sum_p g_vpart[p][b][h].  8192 float4 outputs.
// grid 32, block 256. 64 independent L2 loads per thread.
// ---------------------------------------------------------------------------
__global__ void k1b_reduce() {
    const int idx = blockIdx.x * 256 + threadIdx.x;   // 0..8191 float4 index
    const int b  = idx / H4;
    const int h4 = idx % H4;
    float4 s = make_float4(0.f, 0.f, 0.f, 0.f);
    #pragma unroll 8
    for (int p = 0; p < GCH; p++) {
        const float4 v = *(const float4*)&g_vpart[p][b][h4 * 4];
        s.x += v.x; s.y += v.y; s.z += v.z; s.w += v.w;
    }
    *(float4*)&g_v[b][h4 * 4] = s;
}

// ---------------------------------------------------------------------------
// K2: energies[b][l] = dot(enc[l,b,:], v[b,:])
// grid (LTILES=32, B), block 256 (8 warps, 8 l's per warp, 4 at a time).
// ---------------------------------------------------------------------------
__global__ void k2_energy(const float* __restrict__ enc) {
    const int b  = blockIdx.y;
    const int l0 = blockIdx.x * LPT;
    const int tid = threadIdx.x;

    __shared__ float4 vsh[H4];   // 4 KB
    vsh[tid] = *(const float4*)&g_v[b][tid * 4];
    __syncthreads();

    const int warp = tid >> 5, lane = tid & 31;
    const float4* __restrict__ enc4 = (const float4*)enc;

    #pragma unroll
    for (int i = 0; i < LPW; i += 4) {
        const int la = l0 + warp * LPW + i;
        size_t base[4];
        #pragma unroll
        for (int j = 0; j < 4; j++)
            base[j] = ((size_t)(la + j) * B + b) * H4;
        float a0 = 0.f, a1 = 0.f, a2 = 0.f, a3 = 0.f;
        #pragma unroll
        for (int k = 0; k < 8; k++) {
            const float4 v  = vsh[k * 32 + lane];
            const float4 e0 = __ldcs(&enc4[base[0] + k * 32 + lane]);
            const float4 e1 = __ldcs(&enc4[base[1] + k * 32 + lane]);
            const float4 e2 = __ldcs(&enc4[base[2] + k * 32 + lane]);
            const float4 e3 = __ldcs(&enc4[base[3] + k * 32 + lane]);
            a0 += e0.x * v.x + e0.y * v.y + e0.z * v.z + e0.w * v.w;
            a1 += e1.x * v.x + e1.y * v.y + e1.z * v.z + e1.w * v.w;
            a2 += e2.x * v.x + e2.y * v.y + e2.z * v.z + e2.w * v.w;
            a3 += e3.x * v.x + e3.y * v.y + e3.z * v.z + e3.w * v.w;
        }
        #pragma unroll
        for (int s = 16; s; s >>= 1) {
            a0 += __shfl_down_sync(0xffffffffu, a0, s);
            a1 += __shfl_down_sync(0xffffffffu, a1, s);
            a2 += __shfl_down_sync(0xffffffffu, a2, s);
            a3 += __shfl_down_sync(0xffffffffu, a3, s);
        }
        if (lane == 0) {
            g_energy[b][la + 0] = a0;
            g_energy[b][la + 1] = a1;
            g_energy[b][la + 2] = a2;
            g_energy[b][la + 3] = a3;
        }
    }
}

// ---------------------------------------------------------------------------
// K3: masked softmax per batch row. grid B, block 1024, 2 l's per thread.
// ---------------------------------------------------------------------------
__global__ void k3_softmax(const int* __restrict__ lengths,
                           float* __restrict__ out) {
    const int b   = blockIdx.x;
    const int len = lengths[b];
    const int tid = threadIdx.x;

    float e0 = g_energy[b][tid];
    float e1 = g_energy[b][tid + 1024];
    float mx = -3.4e38f;
    if (tid        < len) mx = e0;
    if (tid + 1024 < len) mx = fmaxf(mx, e1);

    __shared__ float red[32];
    #pragma unroll
    for (int s = 16; s; s >>= 1)
        mx = fmaxf(mx, __shfl_xor_sync(0xffffffffu, mx, s));
    if ((tid & 31) == 0) red[tid >> 5] = mx;
    __syncthreads();
    if (tid < 32) {
        float m = red[tid];
        #pragma unroll
        for (int s = 16; s; s >>= 1)
            m = fmaxf(m, __shfl_xor_sync(0xffffffffu, m, s));
        red[tid] = m;
    }
    __syncthreads();
    mx = red[0];
    __syncthreads();   // protect red[] before reuse

    const float x0 = (tid        < len) ? expf(e0 - mx) : 0.f;
    const float x1 = (tid + 1024 < len) ? expf(e1 - mx) : 0.f;
    float sum = x0 + x1;
    #pragma unroll
    for (int s = 16; s; s >>= 1)
        sum += __shfl_xor_sync(0xffffffffu, sum, s);
    if ((tid & 31) == 0) red[tid >> 5] = sum;
    __syncthreads();
    if (tid < 32) {
        float m = red[tid];
        #pragma unroll
        for (int s = 16; s; s >>= 1)
            m += __shfl_xor_sync(0xffffffffu, m, s);
        red[tid] = m;
    }
    __syncthreads();
    const float inv = 1.f / red[0];

    out[(size_t)b * L + tid]        = x0 * inv;
    out[(size_t)b * L + tid + 1024] = x1 * inv;
}

// ---------------------------------------------------------------------------
extern "C" void kernel_launch(void* const* d_in, const int* in_sizes, int n_in,
                              void* d_out, int out_size) {
    const float* hidden  = (const float*)d_in[0];   // [1,B,H]
    const float* enc     = (const float*)d_in[1];   // [L,B,H]
    const float* W       = (const float*)d_in[2];   // [H,H]
    // d_in[3] = bias — provably cancels in softmax, unused
    const int*   lengths = (const int*)d_in[4];     // [B]
    float* out = (float*)d_out;                     // [B,1,L]

    dim3 g1(H / 256, GCH);
    k1_proj<<<g1, 256>>>(hidden, W);

    k1b_reduce<<<32, 256>>>();

    dim3 g2(LTILES, B);
    k2_energy<<<g2, 256>>>(enc);

    k3_softmax<<<B, 1024>>>(lengths, out);
}

// round 4
// speedup vs baseline: 1.3423x; 1.0762x over previous
#include <cuda_runtime.h>

#define L 2048
#define B 32
#define H 1024
#define H4 (H / 4)
#define LTILES 64
#define LPT (L / LTILES)  // 32 l-positions per K2 block
// K1 geometry
#define K1_HQ 16          // float4 h-quads per block (64 h-cols)
#define K1_SL 16          // g-slices (64 g each)
#define K1_BB 4           // b's per block

// Scratch (allocation-free rule: __device__ globals)
__device__ float g_v[B][H];            // 128 KB reduced v = hidden @ W
__device__ float g_energy[B][L];       // 256 KB energies

// ---------------------------------------------------------------------------
// K1: g_v[b][h] = sum_g hidden[b,g] * W[g,h]   (single kernel, no partials)
// grid (H/64=16, B/4=8) = 128 blocks, block 256 = 16 h-quads x 16 g-slices.
// Thread: 64 independent LDG.128 of W, 4 b-accumulators; smem-reduce slices.
// ---------------------------------------------------------------------------
__global__ void k1_proj(const float* __restrict__ hidden,
                        const float* __restrict__ W) {
    const int tid = threadIdx.x;
    const int hq  = tid & 15;             // 0..15 h-quad within block
    const int sl  = tid >> 4;             // 0..15 g-slice
    const int hq_glob = blockIdx.x * 16 + hq;   // float4 index into row
    const int b0  = blockIdx.y * K1_BB;
    const int g0  = sl * 64;

    __shared__ float hsh[K1_BB][H];       // 16 KB hidden rows
    for (int i = tid; i < K1_BB * H4; i += 256) {
        const int bb = i / H4, g4 = i % H4;
        ((float4*)hsh[bb])[g4] = ((const float4*)hidden)[(size_t)(b0 + bb) * H4 + g4];
    }
    __syncthreads();

    float4 acc[K1_BB];
    #pragma unroll
    for (int j = 0; j < K1_BB; j++) acc[j] = make_float4(0.f, 0.f, 0.f, 0.f);

    const float4* __restrict__ W4 = (const float4*)W;
    #pragma unroll 8
    for (int g = 0; g < 64; g++) {
        const float4 w = W4[(size_t)(g0 + g) * H4 + hq_glob];
        #pragma unroll
        for (int j = 0; j < K1_BB; j++) {
            const float hv = hsh[j][g0 + g];   // smem broadcast
            acc[j].x += w.x * hv; acc[j].y += w.y * hv;
            acc[j].z += w.z * hv; acc[j].w += w.w * hv;
        }
    }

    __shared__ float4 part[K1_SL][K1_BB][K1_HQ];   // 16 KB
    #pragma unroll
    for (int j = 0; j < K1_BB; j++) part[sl][j][hq] = acc[j];
    __syncthreads();

    if (tid < K1_BB * K1_HQ) {            // 64 reducer threads
        const int j = tid >> 4, hq2 = tid & 15;
        float4 s = make_float4(0.f, 0.f, 0.f, 0.f);
        #pragma unroll
        for (int s2 = 0; s2 < K1_SL; s2++) {
            const float4 p = part[s2][j][hq2];
            s.x += p.x; s.y += p.y; s.z += p.z; s.w += p.w;
        }
        *(float4*)&g_v[b0 + j][(blockIdx.x * 16 + hq2) * 4] = s;
    }
}

// ---------------------------------------------------------------------------
// K2: energies[b][l] = dot(enc[l,b,:], v[b,:])
// grid (LTILES=64, B) = 2048 blocks, block 256 (8 warps x 4 l's each).
// ---------------------------------------------------------------------------
__global__ void k2_energy(const float* __restrict__ enc) {
    const int b  = blockIdx.y;
    const int l0 = blockIdx.x * LPT;
    const int tid = threadIdx.x;

    __shared__ float4 vsh[H4];   // 4 KB
    vsh[tid] = *(const float4*)&g_v[b][tid * 4];
    __syncthreads();

    const int warp = tid >> 5, lane = tid & 31;
    const float4* __restrict__ enc4 = (const float4*)enc;

    const int la = l0 + warp * 4;
    size_t base[4];
    #pragma unroll
    for (int j = 0; j < 4; j++)
        base[j] = ((size_t)(la + j) * B + b) * H4;

    float a0 = 0.f, a1 = 0.f, a2 = 0.f, a3 = 0.f;
    #pragma unroll
    for (int k = 0; k < 8; k++) {
        const float4 v  = vsh[k * 32 + lane];
        const float4 e0 = __ldcs(&enc4[base[0] + k * 32 + lane]);
        const float4 e1 = __ldcs(&enc4[base[1] + k * 32 + lane]);
        const float4 e2 = __ldcs(&enc4[base[2] + k * 32 + lane]);
        const float4 e3 = __ldcs(&enc4[base[3] + k * 32 + lane]);
        a0 += e0.x * v.x + e0.y * v.y + e0.z * v.z + e0.w * v.w;
        a1 += e1.x * v.x + e1.y * v.y + e1.z * v.z + e1.w * v.w;
        a2 += e2.x * v.x + e2.y * v.y + e2.z * v.z + e2.w * v.w;
        a3 += e3.x * v.x + e3.y * v.y + e3.z * v.z + e3.w * v.w;
    }
    #pragma unroll
    for (int s = 16; s; s >>= 1) {
        a0 += __shfl_down_sync(0xffffffffu, a0, s);
        a1 += __shfl_down_sync(0xffffffffu, a1, s);
        a2 += __shfl_down_sync(0xffffffffu, a2, s);
        a3 += __shfl_down_sync(0xffffffffu, a3, s);
    }
    if (lane == 0) {
        g_energy[b][la + 0] = a0;
        g_energy[b][la + 1] = a1;
        g_energy[b][la + 2] = a2;
        g_energy[b][la + 3] = a3;
    }
}

// ---------------------------------------------------------------------------
// K3: masked softmax per batch row. grid B, block 512, float4 per thread.
// out[b,0,l] = valid ? exp(e - max)/sum : 0
// ---------------------------------------------------------------------------
__global__ void k3_softmax(const int* __restrict__ lengths,
                           float* __restrict__ out) {
    const int b   = blockIdx.x;
    const int len = lengths[b];
    const int tid = threadIdx.x;
    const int l0  = tid * 4;

    const float4 e = ((const float4*)&g_energy[b][0])[tid];

    float mx = -3.4e38f;
    if (l0 + 0 < len) mx = e.x;
    if (l0 + 1 < len) mx = fmaxf(mx, e.y);
    if (l0 + 2 < len) mx = fmaxf(mx, e.z);
    if (l0 + 3 < len) mx = fmaxf(mx, e.w);

    __shared__ float red_m[16], red_s[16];
    #pragma unroll
    for (int s = 16; s; s >>= 1)
        mx = fmaxf(mx, __shfl_xor_sync(0xffffffffu, mx, s));
    if ((tid & 31) == 0) red_m[tid >> 5] = mx;
    __syncthreads();
    if (tid < 32) {
        float m = (tid < 16) ? red_m[tid] : -3.4e38f;
        #pragma unroll
        for (int s = 8; s; s >>= 1)
            m = fmaxf(m, __shfl_xor_sync(0xffffffffu, m, s));
        if (tid == 0) red_m[0] = m;
    }
    __syncthreads();
    mx = red_m[0];

    float4 x;
    x.x = (l0 + 0 < len) ? expf(e.x - mx) : 0.f;
    x.y = (l0 + 1 < len) ? expf(e.y - mx) : 0.f;
    x.z = (l0 + 2 < len) ? expf(e.z - mx) : 0.f;
    x.w = (l0 + 3 < len) ? expf(e.w - mx) : 0.f;

    float sum = x.x + x.y + x.z + x.w;
    #pragma unroll
    for (int s = 16; s; s >>= 1)
        sum += __shfl_xor_sync(0xffffffffu, sum, s);
    if ((tid & 31) == 0) red_s[tid >> 5] = sum;
    __syncthreads();
    if (tid < 32) {
        float m = (tid < 16) ? red_s[tid] : 0.f;
        #pragma unroll
        for (int s = 8; s; s >>= 1)
            m += __shfl_xor_sync(0xffffffffu, m, s);
        if (tid == 0) red_s[0] = m;
    }
    __syncthreads();
    const float inv = 1.f / red_s[0];

    x.x *= inv; x.y *= inv; x.z *= inv; x.w *= inv;
    ((float4*)(out + (size_t)b * L))[tid] = x;
}

// ---------------------------------------------------------------------------
extern "C" void kernel_launch(void* const* d_in, const int* in_sizes, int n_in,
                              void* d_out, int out_size) {
    const float* hidden  = (const float*)d_in[0];   // [1,B,H]
    const float* enc     = (const float*)d_in[1];   // [L,B,H]
    const float* W       = (const float*)d_in[2];   // [H,H]
    // d_in[3] = bias — provably cancels in softmax, unused
    const int*   lengths = (const int*)d_in[4];     // [B]
    float* out = (float*)d_out;                     // [B,1,L]

    dim3 g1(H / 64, B / K1_BB);
    k1_proj<<<g1, 256>>>(hidden, W);

    dim3 g2(LTILES, B);
    k2_energy<<<g2, 256>>>(enc);

    k3_softmax<<<B, 512>>>(lengths, out);
}